// round 6
// baseline (speedup 1.0000x reference)
#include <cuda_runtime.h>

// PhysicsEngine: B=8, NL=128, NP=8192 pairwise soft-core energy -> 3 scalars/batch.
// Inner iteration = ONE asm block, all packed math as fma.rn.f32x2 (guaranteed
// FFMA2), MUFU unpacks internal to the block so ptxas coalesces the movs.

#define NB 8
#define NL 128
#define NP 8192
#define CHUNK 32
#define NCHUNK (NP / CHUNK)   // 256
#define NPAIR (CHUNK / 2)     // 16

typedef unsigned long long u64;

__device__ float g_part[NB * NCHUNK * 5];
__device__ unsigned g_count = 0;

__device__ __forceinline__ u64 pk(float l, float h) {
    u64 r; asm("mov.b64 %0,{%1,%2};" : "=l"(r) : "f"(l), "f"(h)); return r;
}
__device__ __forceinline__ float f2lo(u64 a) {
    float f; asm("{\n\t.reg .b32 hh;\n\tmov.b64 {%0,hh},%1;\n\t}" : "=f"(f) : "l"(a)); return f;
}
__device__ __forceinline__ float f2hi(u64 a) {
    float f; asm("{\n\t.reg .b32 ll;\n\tmov.b64 {ll,%0},%1;\n\t}" : "=f"(f) : "l"(a)); return f;
}
__device__ __forceinline__ u64 bc(float v) { return pk(v, v); }

__global__ __launch_bounds__(NL) void pe_fused_kernel(
    const float* __restrict__ pos_L, const float* __restrict__ pos_P,
    const float* __restrict__ q_L,   const float* __restrict__ q_P,
    const float* __restrict__ x_L,   const float* __restrict__ x_P,
    const float* __restrict__ vdw_radii, const float* __restrict__ epsilon,
    float* __restrict__ out)
{
    const int c = blockIdx.x;            // protein chunk
    const int b = blockIdx.y;            // batch
    const int l = threadIdx.x;           // ligand index

    // ---- stage protein chunk into SMEM: [A(16) | B(16) | C(16)] longlong2 ----
    // A[jj] = {(-px0,-px1), (-py0,-py1)}
    // B[jj] = {(-pz0,-pz1), ( q0,  q1)}
    // C[jj] = {(rad0,rad1), ( x00, x01)}
    __shared__ longlong2 sAll[3 * NPAIR];
    if (threadIdx.x < CHUNK) {
        const int p = c * CHUNK + threadIdx.x;
        const float4 xp = *(const float4*)(x_P + ((size_t)b * NP + p) * 4);
        const float rad = fmaf(xp.x, 1.7f, fmaf(xp.y, 1.55f, fmaf(xp.z, 1.52f, xp.w * 1.8f)));
        const int jj = threadIdx.x >> 1, h = threadIdx.x & 1;
        float* a0 = (float*)&sAll[jj];
        float* b0 = (float*)&sAll[NPAIR + jj];
        float* c0 = (float*)&sAll[2 * NPAIR + jj];
        a0[h]     = -pos_P[((size_t)b * NP + p) * 3 + 0];
        a0[2 + h] = -pos_P[((size_t)b * NP + p) * 3 + 1];
        b0[h]     = -pos_P[((size_t)b * NP + p) * 3 + 2];
        b0[2 + h] = q_P[b * NP + p];
        c0[h]     = rad;
        c0[2 + h] = xp.x;
    }

    // ---- per-ligand derived quantities ----
    const float* xl = x_L + ((size_t)b * NL + l) * 9;
    float radL = 0.f, epsd = 0.f;
#pragma unroll
    for (int k = 0; k < 9; k++) {
        float x = xl[k];
        radL = fmaf(x, vdw_radii[k], radL);
        epsd = fmaf(x, epsilon[k],   epsd);
    }
    epsd = fmaxf(epsd, 0.f);
    const u64 C4   = bc(4.f * sqrtf(fmaf(epsd, 0.15f, 1e-8f)));   // 4*eps_ij
    const u64 LX   = bc(pos_L[((size_t)b * NL + l) * 3 + 0]);
    const u64 LY   = bc(pos_L[((size_t)b * NL + l) * 3 + 1]);
    const u64 LZ   = bc(pos_L[((size_t)b * NL + l) * 3 + 2]);
    const u64 QL   = bc(83.015f * q_L[b * NL + l]);               // 332.06/4 * q_L
    const u64 XL0  = bc(xl[0]);
    const u64 RADL = bc(radL);

    const u64 E8   = bc(1e-8f);
    const u64 ONE  = bc(1.f);
    const u64 NEG1 = bc(-1.f);
    const u64 HALF = bc(0.5f);
    const u64 P06  = bc(0.6f);
    const u64 I256 = bc(0.00390625f);
    const u64 K1   = bc(2.8853900817779268f);      // 2*log2(e)
    const u64 K2   = bc(-34.624680981335122f);     // -24*log2(e)
    // exp(-(evr+10)) ~= e^-10*(1 - evr + evr^2/2 - evr^3/6), evr in [-0.52, 0]
    const u64 A3   = bc(-7.566654960414142e-06f);  // -e^-10/6
    const u64 A2   = bc( 2.2699964881242427e-05f); //  e^-10/2
    const u64 A1c  = bc(-4.5399929762484854e-05f); // -e^-10
    const u64 A0   = bc( 4.5399929762484854e-05f); //  e^-10
    const u64 ZERO = 0ull;

    unsigned sbase;
    asm("{ .reg .u64 tt; cvta.to.shared.u64 tt, %1; cvt.u32.u64 %0, tt; }"
        : "=r"(sbase) : "l"(sAll));

    __syncthreads();

    u64 s_main = 0ull, s_diff = 0ull, s_hsa = 0ull;   // packed accumulators
    float sp_l = 0.f, sp_h = 0.f, sg_l = 0.f, sg_h = 0.f;

#pragma unroll 8
    for (int jj = 0; jj < NPAIR; jj++) {
        const unsigned addr = sbase + jj * 16;
        asm volatile(
            "{\n\t"
            ".reg .b64 A0,A1,B0,B1,C0,C1,dx,dy,dz,t,iv,ds,sg,sq,is,ee,ra,"
            "r2,r4,r6,rm,ev,ex,tq,em,Ax,Rr,mk,tm;\n\t"
            ".reg .f32 l0,h0,l1,h1;\n\t"
            "ld.shared.v2.u64 {A0,A1},[%7];\n\t"
            "ld.shared.v2.u64 {B0,B1},[%7+256];\n\t"
            "ld.shared.v2.u64 {C0,C1},[%7+512];\n\t"
            "fma.rn.f32x2 dx,%8,%16,A0;\n\t"          // lx - px
            "fma.rn.f32x2 dy,%9,%16,A1;\n\t"
            "fma.rn.f32x2 dz,%10,%16,B0;\n\t"
            "fma.rn.f32x2 t,dz,dz,%15;\n\t"           // dsq + 1e-8
            "fma.rn.f32x2 t,dy,dy,t;\n\t"
            "fma.rn.f32x2 t,dx,dx,t;\n\t"
            "mov.b64 {l0,h0},t;\n\t"
            "rsqrt.approx.f32 l1,l0;\n\t"
            "rsqrt.approx.f32 h1,h0;\n\t"
            "mov.b64 iv,{l1,h1};\n\t"
            "fma.rn.f32x2 ds,t,iv,%27;\n\t"           // dist
            "fma.rn.f32x2 sg,%11,%16,C0;\n\t"         // sigma
            "fma.rn.f32x2 sq,sg,sg,t;\n\t"            // soft^2
            "mov.b64 {l0,h0},sq;\n\t"
            "rsqrt.approx.f32 l1,l0;\n\t"
            "rsqrt.approx.f32 h1,h0;\n\t"
            "mov.b64 is,{l1,h1};\n\t"                 // 1/soft
            "fma.rn.f32x2 ee,%12,B1,%27;\n\t"         // qL*qP*83.015
            "fma.rn.f32x2 ee,ee,is,%27;\n\t"          // e_elec
            "fma.rn.f32x2 ra,sg,is,%27;\n\t"          // ratio <= 1
            "fma.rn.f32x2 r2,ra,ra,%27;\n\t"
            "fma.rn.f32x2 r4,r2,r2,%27;\n\t"
            "fma.rn.f32x2 r6,r4,r2,%27;\n\t"
            "fma.rn.f32x2 rm,r6,%16,%17;\n\t"         // r6 - 1
            "fma.rn.f32x2 ev,r6,rm,%27;\n\t"
            "fma.rn.f32x2 ev,ev,%14,%27;\n\t"         // e_vdw_raw in [-0.52,0]
            "fma.rn.f32x2 ex,ev,%23,%24;\n\t"         // cubic exp(-(evr+10))
            "fma.rn.f32x2 ex,ev,ex,%25;\n\t"
            "fma.rn.f32x2 ex,ev,ex,%26;\n\t"
            "fma.rn.f32x2 tq,ds,%21,%22;\n\t"         // 2log2e*d - 24log2e
            "mov.b64 {l0,h0},tq;\n\t"
            "ex2.approx.f32 l1,l0;\n\t"
            "ex2.approx.f32 h1,h0;\n\t"
            "mov.b64 em,{l1,h1};\n\t"                 // exp(2d-24)
            "fma.rn.f32x2 tm,t,t,%27;\n\t"            // dsq^2
            "fma.rn.f32x2 Ax,tm,%20,%16;\n\t"         // A = 1 + dsq^2/256
            "fma.rn.f32x2 tq,em,%16,%16;\n\t"         // 1+em
            "fma.rn.f32x2 tq,Ax,tq,%27;\n\t"
            "mov.b64 {l0,h0},tq;\n\t"
            "rcp.approx.f32 l1,l0;\n\t"
            "rcp.approx.f32 h1,h0;\n\t"
            "mov.b64 Rr,{l1,h1};\n\t"                 // R = hsa*mask
            "fma.rn.f32x2 mk,Rr,Ax,%27;\n\t"          // mask
            "fma.rn.f32x2 tm,ee,%16,ev;\n\t"
            "fma.rn.f32x2 tm,tm,%16,ex;\n\t"
            "fma.rn.f32x2 %0,tm,mk,%0;\n\t"           // s_main
            "fma.rn.f32x2 %1,ex,mk,%1;\n\t"           // s_diff
            "fma.rn.f32x2 tm,%13,C1,%27;\n\t"         // xl0*xp0
            "fma.rn.f32x2 %2,tm,Rr,%2;\n\t"           // s_hsa
            "fma.rn.f32x2 tq,ds,%17,%27;\n\t"         // -dist
            "fma.rn.f32x2 tm,sg,%19,tq;\n\t"          // 0.6*sigma - dist
            "fma.rn.f32x2 tq,tq,%16,%18;\n\t"         // 0.5 - dist
            "mov.b64 {l0,h0},tm;\n\t"
            "max.f32 l0,l0,0f00000000;\n\t"
            "max.f32 h0,h0,0f00000000;\n\t"
            "fma.rn.f32 %3,l0,l0,%3;\n\t"
            "fma.rn.f32 %4,h0,h0,%4;\n\t"
            "mov.b64 {l0,h0},tq;\n\t"
            "max.f32 l0,l0,0f00000000;\n\t"
            "max.f32 h0,h0,0f00000000;\n\t"
            "fma.rn.f32 %5,l0,l0,%5;\n\t"
            "fma.rn.f32 %6,h0,h0,%6;\n\t"
            "}\n\t"
            : "+l"(s_main), "+l"(s_diff), "+l"(s_hsa),
              "+f"(sp_l), "+f"(sp_h), "+f"(sg_l), "+f"(sg_h)
            : "r"(addr), "l"(LX), "l"(LY), "l"(LZ), "l"(RADL), "l"(QL),
              "l"(XL0), "l"(C4), "l"(E8), "l"(ONE), "l"(NEG1), "l"(HALF),
              "l"(P06), "l"(I256), "l"(K1), "l"(K2), "l"(A3), "l"(A2),
              "l"(A1c), "l"(A0), "l"(ZERO));
    }

    // ---- combine packed halves, then deterministic block reduction ----
    float v[5];
    v[0] = f2lo(s_main) + f2hi(s_main);
    v[1] = f2lo(s_diff) + f2hi(s_diff);
    v[2] = f2lo(s_hsa)  + f2hi(s_hsa);
    v[3] = sp_l + sp_h;
    v[4] = sg_l + sg_h;
#pragma unroll
    for (int k = 0; k < 5; k++) {
#pragma unroll
        for (int off = 16; off > 0; off >>= 1)
            v[k] += __shfl_down_sync(0xffffffffu, v[k], off);
    }
    __shared__ float wred[4][5];
    const int wid = threadIdx.x >> 5, lane = threadIdx.x & 31;
    if (lane == 0) {
#pragma unroll
        for (int k = 0; k < 5; k++) wred[wid][k] = v[k];
    }
    __syncthreads();
    if (threadIdx.x == 0) {
#pragma unroll
        for (int k = 0; k < 5; k++)
            g_part[(b * NCHUNK + c) * 5 + k] =
                wred[0][k] + wred[1][k] + wred[2][k] + wred[3][k];
    }

    // ---- last block finalizes ----
    __shared__ bool is_last;
    if (threadIdx.x == 0) {
        __threadfence();
        unsigned done = atomicAdd(&g_count, 1u);
        is_last = (done == (unsigned)(gridDim.x * gridDim.y) - 1u);
    }
    __syncthreads();
    if (!is_last) return;

    __shared__ float acc[NB][5];
    for (int task = wid; task < NB * 5; task += 4) {
        const int tb = task / 5, tk = task % 5;
        float s = 0.f;
#pragma unroll
        for (int cc = lane; cc < NCHUNK; cc += 32)
            s += g_part[(tb * NCHUNK + cc) * 5 + tk];
#pragma unroll
        for (int off = 16; off > 0; off >>= 1)
            s += __shfl_down_sync(0xffffffffu, s, off);
        if (lane == 0) acc[tb][tk] = s;
    }
    __syncthreads();
    if (threadIdx.x < NB) {
        const int w = threadIdx.x;
        const float s_m = acc[w][0], s_d = acc[w][1], s_h = acc[w][2],
                    s_p = acc[w][3], s_g = acc[w][4];
        const float e_hsa5  = -2.5f * s_h;                    // 5 * (-0.5 * s_hsa)
        const float e_pauli = 11.920292202211755f * s_p;      // 100*sigmoid(-2)
        const float e_ghost = 500.f * s_g;

        out[w] = s_m + e_hsa5 + e_pauli + e_ghost;            // e_raw

        const float e_hard = fminf(e_pauli + e_ghost, 10000.f);
        out[8 + w] = e_hard;

        float log_soft = (s_m - s_d) + e_hsa5;
        float e_soft_final = fminf(fmaxf(log_soft, -500.f), 5000.f);
        out[16 + w] = fminf(e_soft_final + e_hard, 1000000.f);
    }
    if (threadIdx.x == 0) g_count = 0;   // reset for next graph replay
}

extern "C" void kernel_launch(void* const* d_in, const int* in_sizes, int n_in,
                              void* d_out, int out_size)
{
    const float* pos_L = (const float*)d_in[0];
    const float* pos_P = (const float*)d_in[1];
    const float* q_L   = (const float*)d_in[2];
    const float* q_P   = (const float*)d_in[3];
    const float* x_L   = (const float*)d_in[4];
    const float* x_P   = (const float*)d_in[5];
    const float* vdw   = (const float*)d_in[6];
    const float* eps   = (const float*)d_in[7];

    dim3 grid(NCHUNK, NB);
    pe_fused_kernel<<<grid, NL>>>(pos_L, pos_P, q_L, q_P, x_L, x_P, vdw, eps,
                                  (float*)d_out);
}